// round 13
// baseline (speedup 1.0000x reference)
#include <cuda_runtime.h>
#include <cuda_bf16.h>
#include <cuda_fp16.h>
#include <cstdint>
#include <cstring>

#define NN 100000
#define HALF_N 50000
#define EE 1200000
#define GG 128

// Scratch (device globals: no allocation anywhere)
__device__ __align__(16) __half g_xpad[NN * 32];
__device__ __align__(16) __half g_hbuf[NN * 64];
__device__ __align__(16) uint16_t g_aggh[NN * 64];
__device__ int   g_deg[NN];
__device__ int   g_off[NN];
__device__ int   g_cur[NN];
__device__ int   g_edge[EE];
__device__ int   g_part[100352];   // 98*1024 block-scanned partials
__device__ int   g_bsum[128];

// ---------------------------------------------------------------------------
// Helpers
// ---------------------------------------------------------------------------
__device__ __forceinline__ uint32_t smem_u32(const void* p) {
    uint32_t a;
    asm("{ .reg .u64 t; cvta.to.shared.u64 t, %1; cvt.u32.u64 %0, t; }"
        : "=r"(a) : "l"(p));
    return a;
}

// Swizzled row base: swz(row*128 + kb) == rb(row) ^ kb  for kb < 128 (no carry)
__device__ __forceinline__ uint32_t rb(int row) {
    return (uint32_t)(row * 128) ^ (((uint32_t)row & 7u) << 4);
}

__device__ __forceinline__ void ldm_x4(uint32_t r[4], uint32_t addr) {
    asm volatile("ldmatrix.sync.aligned.m8n8.x4.shared.b16 {%0,%1,%2,%3}, [%4];"
                 : "=r"(r[0]), "=r"(r[1]), "=r"(r[2]), "=r"(r[3]) : "r"(addr));
}

__device__ __forceinline__ void mma_bf16(float c[4], const uint32_t a[4],
                                         uint32_t b0, uint32_t b1) {
    asm volatile(
        "mma.sync.aligned.m16n8k16.row.col.f32.bf16.bf16.f32 "
        "{%0,%1,%2,%3}, {%4,%5,%6,%7}, {%8,%9}, {%0,%1,%2,%3};"
        : "+f"(c[0]), "+f"(c[1]), "+f"(c[2]), "+f"(c[3])
        : "r"(a[0]), "r"(a[1]), "r"(a[2]), "r"(a[3]), "r"(b0), "r"(b1));
}

__device__ __forceinline__ void split_bf16(float v, __nv_bfloat16& h, __nv_bfloat16& l) {
    h = __float2bfloat16_rn(v);
    l = __float2bfloat16_rn(v - __bfloat162float(h));
}

// Split+pack two floats: returns hi-pair (bf16x2 bits), writes lo-pair.
__device__ __forceinline__ uint32_t packsplit(float a, float b, uint32_t& lopack) {
    __nv_bfloat16 ha, la, hb, lb;
    split_bf16(a, ha, la);
    split_bf16(b, hb, lb);
    uint16_t ua, ub, va, vb;
    memcpy(&ua, &ha, 2); memcpy(&ub, &hb, 2);
    memcpy(&va, &la, 2); memcpy(&vb, &lb, 2);
    lopack = (uint32_t)va | ((uint32_t)vb << 16);
    return (uint32_t)ua | ((uint32_t)ub << 16);
}

// Pack two floats as plain bf16x2.
__device__ __forceinline__ uint32_t packbf2(float a, float b) {
    __nv_bfloat162 p = __floats2bfloat162_rn(a, b);
    uint32_t u;
    memcpy(&u, &p, 4);
    return u;
}

// Accumulate one fp16 row chunk (uint4 = 8 halves) into fp32 acc[8].
__device__ __forceinline__ void accrow(float acc[8], const uint4& u) {
    const __half2* p = (const __half2*)&u;
#pragma unroll
    for (int j = 0; j < 4; j++) {
        float2 f = __half22float2(p[j]);
        acc[j * 2 + 0] += f.x;
        acc[j * 2 + 1] += f.y;
    }
}

// ---------------------------------------------------------------------------
// CSR build + prep
// ---------------------------------------------------------------------------
__global__ void pad_init_kernel(const float* __restrict__ x,
                                __half* __restrict__ xpad,
                                int* __restrict__ deg) {
    int i = blockIdx.x * blockDim.x + threadIdx.x;
    if (i >= NN * 32) return;
    int n = i >> 5, c = i & 31;
    xpad[i] = __float2half(c < 30 ? x[n * 30 + c] : 0.0f);
    if (c == 0) deg[n] = 0;
}

__global__ void count_deg_kernel(const int* __restrict__ dst, int* __restrict__ deg,
                                 float* __restrict__ outp,
                                 const float* __restrict__ b_out) {
    int e = blockIdx.x * blockDim.x + threadIdx.x;
    if (e < EE) atomicAdd(&deg[__ldg(dst + e)], 1);
    if (blockIdx.x == 0 && threadIdx.x < GG) outp[threadIdx.x] = b_out[0];
}

__global__ void scan_block_kernel(const int* __restrict__ deg,
                                  int* __restrict__ part, int* __restrict__ bsum) {
    __shared__ int sh[1024];
    int tid = threadIdx.x;
    int gid = blockIdx.x * 1024 + tid;
    int v = (gid < NN) ? deg[gid] : 0;
    sh[tid] = v;
    __syncthreads();
    for (int ofs = 1; ofs < 1024; ofs <<= 1) {
        int t = 0;
        if (tid >= ofs) t = sh[tid - ofs];
        __syncthreads();
        if (tid >= ofs) sh[tid] += t;
        __syncthreads();
    }
    part[gid] = sh[tid] - v;   // exclusive
    if (tid == 1023) bsum[blockIdx.x] = sh[1023];
}

__global__ void scan_add_kernel(const int* __restrict__ part,
                                const int* __restrict__ bsum,
                                int* __restrict__ off, int* __restrict__ cur) {
    __shared__ int sh[128];
    int tid = threadIdx.x;
    if (tid < 128) {
        int v = (tid < 98) ? bsum[tid] : 0;
        sh[tid] = v;
    }
    __syncthreads();
    if (tid < 128) {
        for (int ofs = 1; ofs < 128; ofs <<= 1) {
            int t = 0;
            if (tid >= ofs) t = sh[tid - ofs];
            __syncthreads();
            if (tid >= ofs) sh[tid] += t;
            __syncthreads();
        }
    } else {
        for (int ofs = 1; ofs < 128; ofs <<= 1) { __syncthreads(); __syncthreads(); }
    }
    __syncthreads();
    int gid = blockIdx.x * 1024 + tid;
    if (gid >= NN) return;
    int blk_excl = (blockIdx.x == 0) ? 0 : sh[blockIdx.x - 1];
    int o = part[gid] + blk_excl;
    off[gid] = o;
    cur[gid] = o;
}

__global__ void place_kernel(const int* __restrict__ src, const int* __restrict__ dst,
                             int* __restrict__ cur, int* __restrict__ edge) {
    int e = blockIdx.x * blockDim.x + threadIdx.x;
    if (e >= EE) return;
    int d = __ldg(dst + e);
    int p = atomicAdd(&cur[d], 1);
    edge[p] = __ldg(src + e);
}

// ---------------------------------------------------------------------------
// Gather (dual-node): each thread owns nodes gn and gn+HALF_N; the main loop
// interleaves 4 edges from each -> 8 independent row loads in flight.
// fp32 accumulate; output plain bf16.
// ---------------------------------------------------------------------------
template <int K>
__global__ __launch_bounds__(256) void gather_kernel(
    const __half* __restrict__ hin,
    uint16_t* __restrict__ agh,
    const int* __restrict__ off, const int* __restrict__ deg,
    const int* __restrict__ edge, const float* __restrict__ eps) {
    constexpr int L = K / 8;             // lanes per node (16B each)
    const int tid = blockIdx.x * 256 + threadIdx.x;
    const int gnA = tid / L;
    const int sub = tid % L;
    if (gnA >= HALF_N) return;
    const int gnB = gnA + HALF_N;

    const float s = 1.0f + __ldg(eps);
    float accA[8], accB[8];
    {
        uint4 ua = *(const uint4*)(hin + (size_t)gnA * K + sub * 8);
        uint4 ub = *(const uint4*)(hin + (size_t)gnB * K + sub * 8);
        const __half2* pa = (const __half2*)&ua;
        const __half2* pb = (const __half2*)&ub;
#pragma unroll
        for (int j = 0; j < 4; j++) {
            float2 fa = __half22float2(pa[j]);
            float2 fb = __half22float2(pb[j]);
            accA[j * 2 + 0] = s * fa.x; accA[j * 2 + 1] = s * fa.y;
            accB[j * 2 + 0] = s * fb.x; accB[j * 2 + 1] = s * fb.y;
        }
    }

    const int e0a = __ldg(off + gnA), dga = __ldg(deg + gnA);
    const int e0b = __ldg(off + gnB), dgb = __ldg(deg + gnB);
    int ea = 0, eb = 0;

    // Main interleaved loop: 4 edges per node -> 8 row loads in flight
    while (ea + 4 <= dga && eb + 4 <= dgb) {
        int sa0 = __ldg(edge + e0a + ea);
        int sa1 = __ldg(edge + e0a + ea + 1);
        int sa2 = __ldg(edge + e0a + ea + 2);
        int sa3 = __ldg(edge + e0a + ea + 3);
        int sb0 = __ldg(edge + e0b + eb);
        int sb1 = __ldg(edge + e0b + eb + 1);
        int sb2 = __ldg(edge + e0b + eb + 2);
        int sb3 = __ldg(edge + e0b + eb + 3);
        uint4 ua0 = *(const uint4*)(hin + (size_t)sa0 * K + sub * 8);
        uint4 ua1 = *(const uint4*)(hin + (size_t)sa1 * K + sub * 8);
        uint4 ua2 = *(const uint4*)(hin + (size_t)sa2 * K + sub * 8);
        uint4 ua3 = *(const uint4*)(hin + (size_t)sa3 * K + sub * 8);
        uint4 ub0 = *(const uint4*)(hin + (size_t)sb0 * K + sub * 8);
        uint4 ub1 = *(const uint4*)(hin + (size_t)sb1 * K + sub * 8);
        uint4 ub2 = *(const uint4*)(hin + (size_t)sb2 * K + sub * 8);
        uint4 ub3 = *(const uint4*)(hin + (size_t)sb3 * K + sub * 8);
        accrow(accA, ua0); accrow(accA, ua1); accrow(accA, ua2); accrow(accA, ua3);
        accrow(accB, ub0); accrow(accB, ub1); accrow(accB, ub2); accrow(accB, ub3);
        ea += 4; eb += 4;
    }
    // Drain A (4-unrolled then scalar)
    for (; ea + 4 <= dga; ea += 4) {
        int s0 = __ldg(edge + e0a + ea);
        int s1 = __ldg(edge + e0a + ea + 1);
        int s2 = __ldg(edge + e0a + ea + 2);
        int s3 = __ldg(edge + e0a + ea + 3);
        uint4 u0 = *(const uint4*)(hin + (size_t)s0 * K + sub * 8);
        uint4 u1 = *(const uint4*)(hin + (size_t)s1 * K + sub * 8);
        uint4 u2 = *(const uint4*)(hin + (size_t)s2 * K + sub * 8);
        uint4 u3 = *(const uint4*)(hin + (size_t)s3 * K + sub * 8);
        accrow(accA, u0); accrow(accA, u1); accrow(accA, u2); accrow(accA, u3);
    }
    for (; ea < dga; ea++) {
        int s0 = __ldg(edge + e0a + ea);
        uint4 u0 = *(const uint4*)(hin + (size_t)s0 * K + sub * 8);
        accrow(accA, u0);
    }
    // Drain B
    for (; eb + 4 <= dgb; eb += 4) {
        int s0 = __ldg(edge + e0b + eb);
        int s1 = __ldg(edge + e0b + eb + 1);
        int s2 = __ldg(edge + e0b + eb + 2);
        int s3 = __ldg(edge + e0b + eb + 3);
        uint4 u0 = *(const uint4*)(hin + (size_t)s0 * K + sub * 8);
        uint4 u1 = *(const uint4*)(hin + (size_t)s1 * K + sub * 8);
        uint4 u2 = *(const uint4*)(hin + (size_t)s2 * K + sub * 8);
        uint4 u3 = *(const uint4*)(hin + (size_t)s3 * K + sub * 8);
        accrow(accB, u0); accrow(accB, u1); accrow(accB, u2); accrow(accB, u3);
    }
    for (; eb < dgb; eb++) {
        int s0 = __ldg(edge + e0b + eb);
        uint4 u0 = *(const uint4*)(hin + (size_t)s0 * K + sub * 8);
        accrow(accB, u0);
    }

    uint4 hv;
    hv.x = packbf2(accA[0], accA[1]);
    hv.y = packbf2(accA[2], accA[3]);
    hv.z = packbf2(accA[4], accA[5]);
    hv.w = packbf2(accA[6], accA[7]);
    *(uint4*)(agh + (size_t)gnA * K + sub * 8) = hv;
    hv.x = packbf2(accB[0], accB[1]);
    hv.y = packbf2(accB[2], accB[3]);
    hv.z = packbf2(accB[4], accB[5]);
    hv.w = packbf2(accB[6], accB[7]);
    *(uint4*)(agh + (size_t)gnB * K + sub * 8) = hv;
}

// ---------------------------------------------------------------------------
// GEMM core: C[2][8][4] += A(bf16) @ (Whi + Wlo), 2-term split.
// ---------------------------------------------------------------------------
template <int KS>
__device__ __forceinline__ void do_gemm(float c[2][8][4],
                                        const uint32_t aB[2],
                                        const uint32_t bBH[4], const uint32_t bBL[4]) {
#pragma unroll
    for (int ks = 0; ks < KS; ks++) {
        const uint32_t kx = ks * 32;
        uint32_t aF[2][4];
#pragma unroll
        for (int m = 0; m < 2; m++) ldm_x4(aF[m], aB[m] ^ kx);
#pragma unroll
        for (int p = 0; p < 4; p++) {
            uint32_t bh[4], bl[4];
            ldm_x4(bh, bBH[p] ^ kx);
            ldm_x4(bl, bBL[p] ^ kx);
#pragma unroll
            for (int s = 0; s < 2; s++) {
                const int nt = 2 * p + s;
#pragma unroll
                for (int m = 0; m < 2; m++) {
                    mma_bf16(c[m][nt], aF[m], bh[s * 2], bh[s * 2 + 1]);
                    mma_bf16(c[m][nt], aF[m], bl[s * 2], bl[s * 2 + 1]);
                }
            }
        }
    }
}

// ---------------------------------------------------------------------------
// Fused GIN MLP: out = relu(A@W1+b1)@W2+b2. Each block stages W1+W2 hi/lo
// ONCE, then processes TPB 128-node tiles (no per-tile W restage/barrier).
// ---------------------------------------------------------------------------
template <int K_IN, bool POOL, int TPB>
__global__ __launch_bounds__(128) void fused_mlp_kernel(
    const uint16_t* __restrict__ Ah,
    const float* __restrict__ W1, const float* __restrict__ b1,
    const float* __restrict__ W2, const float* __restrict__ b2, int w1Rows,
    __half* __restrict__ out,
    const int* __restrict__ batch,
    const float* __restrict__ wout, float* __restrict__ outp) {
    __shared__ __align__(128) char sA[128 * 128];      // 16KB
    __shared__ __align__(128) char sW1_hi[64 * 128];   // 8KB
    __shared__ __align__(128) char sW1_lo[64 * 128];   // 8KB
    __shared__ __align__(128) char sW2_hi[64 * 128];   // 8KB
    __shared__ __align__(128) char sW2_lo[64 * 128];   // 8KB

    const int tid  = threadIdx.x;
    const int warp = tid >> 5;
    const int lane = tid & 31;
    const int qr = lane >> 2;
    const int qc = lane & 3;
    const int g  = lane >> 3;
    const int li = lane & 7;

    const uint32_t sA_u    = smem_u32(sA);
    const uint32_t sW1hi_u = smem_u32(sW1_hi);
    const uint32_t sW1lo_u = smem_u32(sW1_lo);
    const uint32_t sW2hi_u = smem_u32(sW2_hi);
    const uint32_t sW2lo_u = smem_u32(sW2_lo);

    // ---- Stage W1 + W2 transposed (once per block) ----
    for (int i = tid; i < 64 * 32; i += 128) {
        int n = i >> 5, c2 = i & 31;
        int k0 = c2 * 2;
        uint32_t o = rb(n) ^ (uint32_t)(k0 * 2);
        float w0  = (k0     < w1Rows) ? W1[(k0    ) * 64 + n] : 0.0f;
        float w1v = (k0 + 1 < w1Rows) ? W1[(k0 + 1) * 64 + n] : 0.0f;
        uint32_t lo, hi = packsplit(w0, w1v, lo);
        *(uint32_t*)(sW1_hi + o) = hi;
        *(uint32_t*)(sW1_lo + o) = lo;
        hi = packsplit(W2[k0 * 64 + n], W2[(k0 + 1) * 64 + n], lo);
        *(uint32_t*)(sW2_hi + o) = hi;
        *(uint32_t*)(sW2_lo + o) = lo;
    }

    // ---- Precompute ldmatrix lane bases (constant across tiles) ----
    uint32_t aB[2];
#pragma unroll
    for (int m = 0; m < 2; m++) {
        int rowA = warp * 32 + m * 16 + li + (g & 1) * 8;
        uint32_t ka = (uint32_t)((g >> 1) * 16);
        aB[m] = sA_u + (rb(rowA) ^ ka);
    }
    uint32_t b1H[4], b1L[4], b2H[4], b2L[4];
#pragma unroll
    for (int p = 0; p < 4; p++) {
        int rowB = p * 16 + ((g >> 1) & 1) * 8 + li;
        uint32_t kb = (uint32_t)((g & 1) * 16);
        uint32_t r = rb(rowB) ^ kb;
        b1H[p] = sW1hi_u + r;
        b1L[p] = sW1lo_u + r;
        b2H[p] = sW2hi_u + r;
        b2L[p] = sW2lo_u + r;
    }

    constexpr int CH = K_IN / 8;  // 16B chunks of data per row

    for (int t = 0; t < TPB; t++) {
        const int base = (blockIdx.x * TPB + t) * 128;
        if (base >= NN) break;

        // Guard: previous tile's GEMM2 reads of sA must finish (also covers
        // the once-per-block W staging on the first iteration).
        __syncthreads();

        // ---- Stage A: pure 16B copies ----
        for (int idx = tid; idx < 128 * CH; idx += 128) {
            int row = idx / CH, cch = idx % CH;
            int gn = base + row;
            uint4 vh = make_uint4(0, 0, 0, 0);
            if (gn < NN) vh = *(const uint4*)(Ah + (size_t)gn * K_IN + cch * 8);
            *(uint4*)(sA + (rb(row) ^ (uint32_t)(cch * 16))) = vh;
        }
        __syncthreads();

        float c[2][8][4];
#pragma unroll
        for (int m = 0; m < 2; m++)
#pragma unroll
            for (int n = 0; n < 8; n++)
#pragma unroll
                for (int j = 0; j < 4; j++) c[m][n][j] = 0.0f;

        // ---- GEMM1 ----
        do_gemm<K_IN / 16>(c, aB, b1H, b1L);

        // ---- Epilogue 1: h = relu(C+b1) -> bf16 into sA (own-warp rows) ----
#pragma unroll
        for (int m = 0; m < 2; m++) {
            int r0 = warp * 32 + m * 16 + qr;
            uint32_t rb0 = rb(r0), rb1 = rb(r0 + 8);
#pragma unroll
            for (int nt = 0; nt < 8; nt++) {
                uint32_t cb = (uint32_t)(nt * 16 + qc * 4);
                int col = nt * 8 + qc * 2;
                float bv0 = __ldg(b1 + col), bv1 = __ldg(b1 + col + 1);
                float v0 = fmaxf(c[m][nt][0] + bv0, 0.0f);
                float v1 = fmaxf(c[m][nt][1] + bv1, 0.0f);
                float v2 = fmaxf(c[m][nt][2] + bv0, 0.0f);
                float v3 = fmaxf(c[m][nt][3] + bv1, 0.0f);
                *(uint32_t*)(sA + (rb0 ^ cb)) = packbf2(v0, v1);
                *(uint32_t*)(sA + (rb1 ^ cb)) = packbf2(v2, v3);
            }
        }
        // No barrier: GEMM2 reads only this warp's own sA rows.

#pragma unroll
        for (int m = 0; m < 2; m++)
#pragma unroll
            for (int n = 0; n < 8; n++)
#pragma unroll
                for (int j = 0; j < 4; j++) c[m][n][j] = 0.0f;

        // ---- GEMM2 ----
        do_gemm<4>(c, aB, b2H, b2L);

        // ---- Epilogue 2 ----
        if (!POOL) {
#pragma unroll
            for (int m = 0; m < 2; m++) {
                int r0 = warp * 32 + m * 16 + qr;
                int gn0 = base + r0, gn1 = gn0 + 8;
#pragma unroll
                for (int nt = 0; nt < 8; nt++) {
                    int col = nt * 8 + qc * 2;
                    float bv0 = __ldg(b2 + col), bv1 = __ldg(b2 + col + 1);
                    if (gn0 < NN)
                        *(__half2*)(out + (size_t)gn0 * 64 + col) =
                            __floats2half2_rn(c[m][nt][0] + bv0, c[m][nt][1] + bv1);
                    if (gn1 < NN)
                        *(__half2*)(out + (size_t)gn1 * 64 + col) =
                            __floats2half2_rn(c[m][nt][2] + bv0, c[m][nt][3] + bv1);
                }
            }
        } else {
#pragma unroll
            for (int m = 0; m < 2; m++) {
                int r0 = warp * 32 + m * 16 + qr;
                int gn0 = base + r0, gn1 = gn0 + 8;
                float s0 = 0.0f, s1 = 0.0f;
#pragma unroll
                for (int nt = 0; nt < 8; nt++) {
                    int col = nt * 8 + qc * 2;
                    float bv0 = __ldg(b2 + col), bv1 = __ldg(b2 + col + 1);
                    float w0 = __ldg(wout + col), w1 = __ldg(wout + col + 1);
                    s0 += (c[m][nt][0] + bv0) * w0 + (c[m][nt][1] + bv1) * w1;
                    s1 += (c[m][nt][2] + bv0) * w0 + (c[m][nt][3] + bv1) * w1;
                }
                s0 += __shfl_xor_sync(0xFFFFFFFF, s0, 1);
                s0 += __shfl_xor_sync(0xFFFFFFFF, s0, 2);
                s1 += __shfl_xor_sync(0xFFFFFFFF, s1, 1);
                s1 += __shfl_xor_sync(0xFFFFFFFF, s1, 2);
                if (qc == 0) {
                    if (gn0 < NN) atomicAdd(&outp[__ldg(batch + gn0)], s0);
                    if (gn1 < NN) atomicAdd(&outp[__ldg(batch + gn1)], s1);
                }
            }
        }
    }
}

// ---------------------------------------------------------------------------
extern "C" void kernel_launch(void* const* d_in, const int* in_sizes, int n_in,
                              void* d_out, int out_size) {
    const float* x     = (const float*)d_in[0];
    const int*   ei    = (const int*)d_in[1];   // [2, E]
    const int*   batch = (const int*)d_in[2];
    const float* eps0  = (const float*)d_in[3];
    const float* w1_0  = (const float*)d_in[4];
    const float* b1_0  = (const float*)d_in[5];
    const float* w2_0  = (const float*)d_in[6];
    const float* b2_0  = (const float*)d_in[7];
    const float* eps_r = (const float*)d_in[8];
    const float* w1_r  = (const float*)d_in[9];
    const float* b1_r  = (const float*)d_in[10];
    const float* w2_r  = (const float*)d_in[11];
    const float* b2_r  = (const float*)d_in[12];
    const float* w_out = (const float*)d_in[13];
    const float* b_out = (const float*)d_in[14];

    const int* src = ei;
    const int* dst = ei + EE;

    __half *xpad, *hbuf;
    uint16_t *agh;
    int *deg, *off, *cur, *edge, *part, *bsum;
    cudaGetSymbolAddress((void**)&xpad, g_xpad);
    cudaGetSymbolAddress((void**)&hbuf, g_hbuf);
    cudaGetSymbolAddress((void**)&agh,  g_aggh);
    cudaGetSymbolAddress((void**)&deg,  g_deg);
    cudaGetSymbolAddress((void**)&off,  g_off);
    cudaGetSymbolAddress((void**)&cur,  g_cur);
    cudaGetSymbolAddress((void**)&edge, g_edge);
    cudaGetSymbolAddress((void**)&part, g_part);
    cudaGetSymbolAddress((void**)&bsum, g_bsum);

    float* outp = (float*)d_out;
    const int TB = 256;
    constexpr int TPB = 2;
    const int mlp_grid = (NN + 128 * TPB - 1) / (128 * TPB);   // 391
    const int gat32_grid = (HALF_N * 4 + 255) / 256;
    const int gat64_grid = (HALF_N * 8 + 255) / 256;

    // ---- CSR build (one-time) + prep: 5 launches ----
    pad_init_kernel<<<(NN * 32 + TB - 1) / TB, TB>>>(x, xpad, deg);
    count_deg_kernel<<<(EE + TB - 1) / TB, TB>>>(dst, deg, outp, b_out);
    scan_block_kernel<<<98, 1024>>>(deg, part, bsum);
    scan_add_kernel<<<98, 1024>>>(part, bsum, off, cur);
    place_kernel<<<(EE + TB - 1) / TB, TB>>>(src, dst, cur, edge);

    // ---- Layer 0 (K=32) ----
    gather_kernel<32><<<gat32_grid, 256>>>(xpad, agh, off, deg, edge, eps0);
    fused_mlp_kernel<32, false, TPB><<<mlp_grid, 128>>>(agh, w1_0, b1_0, w2_0, b2_0, 30,
                                                        hbuf, nullptr, nullptr, nullptr);
    // ---- Layers 1..2 ----
    for (int i = 0; i < 2; i++) {
        gather_kernel<64><<<gat64_grid, 256>>>(hbuf, agh, off, deg, edge, eps_r + i);
        fused_mlp_kernel<64, false, TPB><<<mlp_grid, 128>>>(agh, w1_r + i * 4096, b1_r + i * 64,
                                                            w2_r + i * 4096, b2_r + i * 64, 64,
                                                            hbuf, nullptr, nullptr, nullptr);
    }
    // ---- Layer 3 (fused pool) ----
    gather_kernel<64><<<gat64_grid, 256>>>(hbuf, agh, off, deg, edge, eps_r + 2);
    fused_mlp_kernel<64, true, TPB><<<mlp_grid, 128>>>(agh, w1_r + 8192, b1_r + 128,
                                                       w2_r + 8192, b2_r + 128, 64,
                                                       nullptr, batch, w_out, outp);
}

// round 15
// speedup vs baseline: 1.0500x; 1.0500x over previous
#include <cuda_runtime.h>
#include <cuda_bf16.h>
#include <cuda_fp16.h>
#include <cstdint>
#include <cstring>

#define NN 100000
#define EE 1200000
#define GG 128

// Scratch (device globals: no allocation anywhere)
__device__ __align__(16) __half g_xpad[NN * 32];
__device__ __align__(16) __half g_hbuf[NN * 64];
__device__ __align__(16) uint16_t g_aggh[NN * 64];
__device__ int   g_deg[NN];
__device__ int   g_off[NN];
__device__ int   g_cur[NN];
__device__ int   g_edge[EE];
__device__ int   g_part[100352];   // 98*1024 block-scanned partials
__device__ int   g_bsum[128];

// ---------------------------------------------------------------------------
// Helpers
// ---------------------------------------------------------------------------
__device__ __forceinline__ uint32_t smem_u32(const void* p) {
    uint32_t a;
    asm("{ .reg .u64 t; cvta.to.shared.u64 t, %1; cvt.u32.u64 %0, t; }"
        : "=r"(a) : "l"(p));
    return a;
}

// Swizzled row base: swz(row*128 + kb) == rb(row) ^ kb  for kb < 128 (no carry)
__device__ __forceinline__ uint32_t rb(int row) {
    return (uint32_t)(row * 128) ^ (((uint32_t)row & 7u) << 4);
}

__device__ __forceinline__ void ldm_x4(uint32_t r[4], uint32_t addr) {
    asm volatile("ldmatrix.sync.aligned.m8n8.x4.shared.b16 {%0,%1,%2,%3}, [%4];"
                 : "=r"(r[0]), "=r"(r[1]), "=r"(r[2]), "=r"(r[3]) : "r"(addr));
}

__device__ __forceinline__ void mma_bf16(float c[4], const uint32_t a[4],
                                         uint32_t b0, uint32_t b1) {
    asm volatile(
        "mma.sync.aligned.m16n8k16.row.col.f32.bf16.bf16.f32 "
        "{%0,%1,%2,%3}, {%4,%5,%6,%7}, {%8,%9}, {%0,%1,%2,%3};"
        : "+f"(c[0]), "+f"(c[1]), "+f"(c[2]), "+f"(c[3])
        : "r"(a[0]), "r"(a[1]), "r"(a[2]), "r"(a[3]), "r"(b0), "r"(b1));
}

__device__ __forceinline__ void split_bf16(float v, __nv_bfloat16& h, __nv_bfloat16& l) {
    h = __float2bfloat16_rn(v);
    l = __float2bfloat16_rn(v - __bfloat162float(h));
}

// Split+pack two floats: returns hi-pair (bf16x2 bits), writes lo-pair.
__device__ __forceinline__ uint32_t packsplit(float a, float b, uint32_t& lopack) {
    __nv_bfloat16 ha, la, hb, lb;
    split_bf16(a, ha, la);
    split_bf16(b, hb, lb);
    uint16_t ua, ub, va, vb;
    memcpy(&ua, &ha, 2); memcpy(&ub, &hb, 2);
    memcpy(&va, &la, 2); memcpy(&vb, &lb, 2);
    lopack = (uint32_t)va | ((uint32_t)vb << 16);
    return (uint32_t)ua | ((uint32_t)ub << 16);
}

// Pack two floats as plain bf16x2.
__device__ __forceinline__ uint32_t packbf2(float a, float b) {
    __nv_bfloat162 p = __floats2bfloat162_rn(a, b);
    uint32_t u;
    memcpy(&u, &p, 4);
    return u;
}

// ---------------------------------------------------------------------------
// CSR build + prep
// ---------------------------------------------------------------------------
__global__ void pad_init_kernel(const float* __restrict__ x,
                                __half* __restrict__ xpad,
                                int* __restrict__ deg) {
    int i = blockIdx.x * blockDim.x + threadIdx.x;
    if (i >= NN * 32) return;
    int n = i >> 5, c = i & 31;
    xpad[i] = __float2half(c < 30 ? x[n * 30 + c] : 0.0f);
    if (c == 0) deg[n] = 0;
}

__global__ void count_deg_kernel(const int* __restrict__ dst, int* __restrict__ deg,
                                 float* __restrict__ outp,
                                 const float* __restrict__ b_out) {
    int e = blockIdx.x * blockDim.x + threadIdx.x;
    if (e < EE) atomicAdd(&deg[__ldg(dst + e)], 1);
    if (blockIdx.x == 0 && threadIdx.x < GG) outp[threadIdx.x] = b_out[0];
}

// Warp-shuffle block scan (2 barriers instead of 20).
__global__ void scan_block_kernel(const int* __restrict__ deg,
                                  int* __restrict__ part, int* __restrict__ bsum) {
    __shared__ int wt[32];
    int tid = threadIdx.x;
    int lane = tid & 31, w = tid >> 5;
    int gid = blockIdx.x * 1024 + tid;
    int v = (gid < NN) ? deg[gid] : 0;

    // Inclusive scan within warp
    int x = v;
#pragma unroll
    for (int ofs = 1; ofs < 32; ofs <<= 1) {
        int t = __shfl_up_sync(0xFFFFFFFF, x, ofs);
        if (lane >= ofs) x += t;
    }
    if (lane == 31) wt[w] = x;
    __syncthreads();
    if (w == 0) {
        int y = wt[lane];
#pragma unroll
        for (int ofs = 1; ofs < 32; ofs <<= 1) {
            int t = __shfl_up_sync(0xFFFFFFFF, y, ofs);
            if (lane >= ofs) y += t;
        }
        wt[lane] = y;
    }
    __syncthreads();
    int pre = (w > 0) ? wt[w - 1] : 0;
    int incl = x + pre;
    part[gid] = incl - v;                 // exclusive
    if (tid == 1023) bsum[blockIdx.x] = incl;
}

// Each block only needs ONE prefix value: sum of bsum[0..blockIdx.x-1].
__global__ void scan_add_kernel(const int* __restrict__ part,
                                const int* __restrict__ bsum,
                                int* __restrict__ off, int* __restrict__ cur) {
    __shared__ int s_prev;
    int tid = threadIdx.x;
    if (tid == 0) {
        int p = 0;
        for (int i = 0; i < blockIdx.x; i++) p += __ldg(bsum + i);
        s_prev = p;
    }
    __syncthreads();
    int gid = blockIdx.x * 1024 + tid;
    if (gid >= NN) return;
    int o = part[gid] + s_prev;
    off[gid] = o;
    cur[gid] = o;
}

__global__ void place_kernel(const int* __restrict__ src, const int* __restrict__ dst,
                             int* __restrict__ cur, int* __restrict__ edge) {
    int e = blockIdx.x * blockDim.x + threadIdx.x;
    if (e >= EE) return;
    int d = __ldg(dst + e);
    int p = atomicAdd(&cur[d], 1);
    edge[p] = __ldg(src + e);
}

// ---------------------------------------------------------------------------
// Gather (R12-proven): acc = (1+eps)*h[n] + sum h[src_e] over fp16 rows;
// K/8 lanes per node (16B each); fp32 accumulate; edge loop unrolled x4;
// output plain bf16 (A-hi only).
// ---------------------------------------------------------------------------
template <int K>
__global__ __launch_bounds__(256) void gather_kernel(
    const __half* __restrict__ hin,
    uint16_t* __restrict__ agh,
    const int* __restrict__ off, const int* __restrict__ deg,
    const int* __restrict__ edge, const float* __restrict__ eps) {
    constexpr int L = K / 8;             // lanes per node (16B each)
    const int tid = blockIdx.x * 256 + threadIdx.x;
    const int gn = tid / L;
    const int sub = tid % L;
    if (gn >= NN) return;

    float acc[8];
    const float s = 1.0f + __ldg(eps);
    {
        uint4 u = *(const uint4*)(hin + (size_t)gn * K + sub * 8);
        const __half2* hp = (const __half2*)&u;
#pragma unroll
        for (int j = 0; j < 4; j++) {
            float2 f = __half22float2(hp[j]);
            acc[j * 2 + 0] = s * f.x;
            acc[j * 2 + 1] = s * f.y;
        }
    }

    const int e0 = __ldg(off + gn);
    const int dg = __ldg(deg + gn);
    int e = 0;
    for (; e + 4 <= dg; e += 4) {
        int sn0 = __ldg(edge + e0 + e);
        int sn1 = __ldg(edge + e0 + e + 1);
        int sn2 = __ldg(edge + e0 + e + 2);
        int sn3 = __ldg(edge + e0 + e + 3);
        uint4 u0 = *(const uint4*)(hin + (size_t)sn0 * K + sub * 8);
        uint4 u1 = *(const uint4*)(hin + (size_t)sn1 * K + sub * 8);
        uint4 u2 = *(const uint4*)(hin + (size_t)sn2 * K + sub * 8);
        uint4 u3 = *(const uint4*)(hin + (size_t)sn3 * K + sub * 8);
        const __half2* p0 = (const __half2*)&u0;
        const __half2* p1 = (const __half2*)&u1;
        const __half2* p2 = (const __half2*)&u2;
        const __half2* p3 = (const __half2*)&u3;
#pragma unroll
        for (int j = 0; j < 4; j++) {
            float2 f0 = __half22float2(p0[j]);
            float2 f1 = __half22float2(p1[j]);
            float2 f2 = __half22float2(p2[j]);
            float2 f3 = __half22float2(p3[j]);
            acc[j * 2 + 0] += (f0.x + f1.x) + (f2.x + f3.x);
            acc[j * 2 + 1] += (f0.y + f1.y) + (f2.y + f3.y);
        }
    }
    for (; e < dg; e++) {
        int sn0 = __ldg(edge + e0 + e);
        uint4 ua = *(const uint4*)(hin + (size_t)sn0 * K + sub * 8);
        const __half2* pa = (const __half2*)&ua;
#pragma unroll
        for (int j = 0; j < 4; j++) {
            float2 fa = __half22float2(pa[j]);
            acc[j * 2 + 0] += fa.x;
            acc[j * 2 + 1] += fa.y;
        }
    }

    uint4 hv;
    hv.x = packbf2(acc[0], acc[1]);
    hv.y = packbf2(acc[2], acc[3]);
    hv.z = packbf2(acc[4], acc[5]);
    hv.w = packbf2(acc[6], acc[7]);
    *(uint4*)(agh + (size_t)gn * K + sub * 8) = hv;
}

// ---------------------------------------------------------------------------
// GEMM core: C[2][8][4] += A(bf16) @ (Whi + Wlo), 2-term split.
// ---------------------------------------------------------------------------
template <int KS>
__device__ __forceinline__ void do_gemm(float c[2][8][4],
                                        const uint32_t aB[2],
                                        const uint32_t bBH[4], const uint32_t bBL[4]) {
#pragma unroll
    for (int ks = 0; ks < KS; ks++) {
        const uint32_t kx = ks * 32;
        uint32_t aF[2][4];
#pragma unroll
        for (int m = 0; m < 2; m++) ldm_x4(aF[m], aB[m] ^ kx);
#pragma unroll
        for (int p = 0; p < 4; p++) {
            uint32_t bh[4], bl[4];
            ldm_x4(bh, bBH[p] ^ kx);
            ldm_x4(bl, bBL[p] ^ kx);
#pragma unroll
            for (int s = 0; s < 2; s++) {
                const int nt = 2 * p + s;
#pragma unroll
                for (int m = 0; m < 2; m++) {
                    mma_bf16(c[m][nt], aF[m], bh[s * 2], bh[s * 2 + 1]);
                    mma_bf16(c[m][nt], aF[m], bl[s * 2], bl[s * 2 + 1]);
                }
            }
        }
    }
}

// ---------------------------------------------------------------------------
// Fused GIN MLP (R12-proven): out = relu(A@W1+b1)@W2+b2. Each block stages
// W1+W2 hi/lo ONCE, then processes TPB 128-node tiles.
// ---------------------------------------------------------------------------
template <int K_IN, bool POOL, int TPB>
__global__ __launch_bounds__(128) void fused_mlp_kernel(
    const uint16_t* __restrict__ Ah,
    const float* __restrict__ W1, const float* __restrict__ b1,
    const float* __restrict__ W2, const float* __restrict__ b2, int w1Rows,
    __half* __restrict__ out,
    const int* __restrict__ batch,
    const float* __restrict__ wout, float* __restrict__ outp) {
    __shared__ __align__(128) char sA[128 * 128];      // 16KB
    __shared__ __align__(128) char sW1_hi[64 * 128];   // 8KB
    __shared__ __align__(128) char sW1_lo[64 * 128];   // 8KB
    __shared__ __align__(128) char sW2_hi[64 * 128];   // 8KB
    __shared__ __align__(128) char sW2_lo[64 * 128];   // 8KB

    const int tid  = threadIdx.x;
    const int warp = tid >> 5;
    const int lane = tid & 31;
    const int qr = lane >> 2;
    const int qc = lane & 3;
    const int g  = lane >> 3;
    const int li = lane & 7;

    const uint32_t sA_u    = smem_u32(sA);
    const uint32_t sW1hi_u = smem_u32(sW1_hi);
    const uint32_t sW1lo_u = smem_u32(sW1_lo);
    const uint32_t sW2hi_u = smem_u32(sW2_hi);
    const uint32_t sW2lo_u = smem_u32(sW2_lo);

    // ---- Stage W1 + W2 transposed (once per block) ----
    for (int i = tid; i < 64 * 32; i += 128) {
        int n = i >> 5, c2 = i & 31;
        int k0 = c2 * 2;
        uint32_t o = rb(n) ^ (uint32_t)(k0 * 2);
        float w0  = (k0     < w1Rows) ? W1[(k0    ) * 64 + n] : 0.0f;
        float w1v = (k0 + 1 < w1Rows) ? W1[(k0 + 1) * 64 + n] : 0.0f;
        uint32_t lo, hi = packsplit(w0, w1v, lo);
        *(uint32_t*)(sW1_hi + o) = hi;
        *(uint32_t*)(sW1_lo + o) = lo;
        hi = packsplit(W2[k0 * 64 + n], W2[(k0 + 1) * 64 + n], lo);
        *(uint32_t*)(sW2_hi + o) = hi;
        *(uint32_t*)(sW2_lo + o) = lo;
    }

    // ---- Precompute ldmatrix lane bases (constant across tiles) ----
    uint32_t aB[2];
#pragma unroll
    for (int m = 0; m < 2; m++) {
        int rowA = warp * 32 + m * 16 + li + (g & 1) * 8;
        uint32_t ka = (uint32_t)((g >> 1) * 16);
        aB[m] = sA_u + (rb(rowA) ^ ka);
    }
    uint32_t b1H[4], b1L[4], b2H[4], b2L[4];
#pragma unroll
    for (int p = 0; p < 4; p++) {
        int rowB = p * 16 + ((g >> 1) & 1) * 8 + li;
        uint32_t kb = (uint32_t)((g & 1) * 16);
        uint32_t r = rb(rowB) ^ kb;
        b1H[p] = sW1hi_u + r;
        b1L[p] = sW1lo_u + r;
        b2H[p] = sW2hi_u + r;
        b2L[p] = sW2lo_u + r;
    }

    constexpr int CH = K_IN / 8;  // 16B chunks of data per row

    for (int t = 0; t < TPB; t++) {
        const int base = (blockIdx.x * TPB + t) * 128;
        if (base >= NN) break;

        // Guard: previous tile's GEMM2 reads of sA must finish (also covers
        // the once-per-block W staging on the first iteration).
        __syncthreads();

        // ---- Stage A: pure 16B copies ----
        for (int idx = tid; idx < 128 * CH; idx += 128) {
            int row = idx / CH, cch = idx % CH;
            int gn = base + row;
            uint4 vh = make_uint4(0, 0, 0, 0);
            if (gn < NN) vh = *(const uint4*)(Ah + (size_t)gn * K_IN + cch * 8);
            *(uint4*)(sA + (rb(row) ^ (uint32_t)(cch * 16))) = vh;
        }
        __syncthreads();

        float c[2][8][4];
#pragma unroll
        for (int m = 0; m < 2; m++)
#pragma unroll
            for (int n = 0; n < 8; n++)
#pragma unroll
                for (int j = 0; j < 4; j++) c[m][n][j] = 0.0f;

        // ---- GEMM1 ----
        do_gemm<K_IN / 16>(c, aB, b1H, b1L);

        // ---- Epilogue 1: h = relu(C+b1) -> bf16 into sA (own-warp rows) ----
#pragma unroll
        for (int m = 0; m < 2; m++) {
            int r0 = warp * 32 + m * 16 + qr;
            uint32_t rb0 = rb(r0), rb1 = rb(r0 + 8);
#pragma unroll
            for (int nt = 0; nt < 8; nt++) {
                uint32_t cb = (uint32_t)(nt * 16 + qc * 4);
                int col = nt * 8 + qc * 2;
                float bv0 = __ldg(b1 + col), bv1 = __ldg(b1 + col + 1);
                float v0 = fmaxf(c[m][nt][0] + bv0, 0.0f);
                float v1 = fmaxf(c[m][nt][1] + bv1, 0.0f);
                float v2 = fmaxf(c[m][nt][2] + bv0, 0.0f);
                float v3 = fmaxf(c[m][nt][3] + bv1, 0.0f);
                *(uint32_t*)(sA + (rb0 ^ cb)) = packbf2(v0, v1);
                *(uint32_t*)(sA + (rb1 ^ cb)) = packbf2(v2, v3);
            }
        }
        // No barrier: GEMM2 reads only this warp's own sA rows.

#pragma unroll
        for (int m = 0; m < 2; m++)
#pragma unroll
            for (int n = 0; n < 8; n++)
#pragma unroll
                for (int j = 0; j < 4; j++) c[m][n][j] = 0.0f;

        // ---- GEMM2 ----
        do_gemm<4>(c, aB, b2H, b2L);

        // ---- Epilogue 2 ----
        if (!POOL) {
#pragma unroll
            for (int m = 0; m < 2; m++) {
                int r0 = warp * 32 + m * 16 + qr;
                int gn0 = base + r0, gn1 = gn0 + 8;
#pragma unroll
                for (int nt = 0; nt < 8; nt++) {
                    int col = nt * 8 + qc * 2;
                    float bv0 = __ldg(b2 + col), bv1 = __ldg(b2 + col + 1);
                    if (gn0 < NN)
                        *(__half2*)(out + (size_t)gn0 * 64 + col) =
                            __floats2half2_rn(c[m][nt][0] + bv0, c[m][nt][1] + bv1);
                    if (gn1 < NN)
                        *(__half2*)(out + (size_t)gn1 * 64 + col) =
                            __floats2half2_rn(c[m][nt][2] + bv0, c[m][nt][3] + bv1);
                }
            }
        } else {
#pragma unroll
            for (int m = 0; m < 2; m++) {
                int r0 = warp * 32 + m * 16 + qr;
                int gn0 = base + r0, gn1 = gn0 + 8;
                float s0 = 0.0f, s1 = 0.0f;
#pragma unroll
                for (int nt = 0; nt < 8; nt++) {
                    int col = nt * 8 + qc * 2;
                    float bv0 = __ldg(b2 + col), bv1 = __ldg(b2 + col + 1);
                    float w0 = __ldg(wout + col), w1 = __ldg(wout + col + 1);
                    s0 += (c[m][nt][0] + bv0) * w0 + (c[m][nt][1] + bv1) * w1;
                    s1 += (c[m][nt][2] + bv0) * w0 + (c[m][nt][3] + bv1) * w1;
                }
                s0 += __shfl_xor_sync(0xFFFFFFFF, s0, 1);
                s0 += __shfl_xor_sync(0xFFFFFFFF, s0, 2);
                s1 += __shfl_xor_sync(0xFFFFFFFF, s1, 1);
                s1 += __shfl_xor_sync(0xFFFFFFFF, s1, 2);
                if (qc == 0) {
                    if (gn0 < NN) atomicAdd(&outp[__ldg(batch + gn0)], s0);
                    if (gn1 < NN) atomicAdd(&outp[__ldg(batch + gn1)], s1);
                }
            }
        }
    }
}

// ---------------------------------------------------------------------------
extern "C" void kernel_launch(void* const* d_in, const int* in_sizes, int n_in,
                              void* d_out, int out_size) {
    const float* x     = (const float*)d_in[0];
    const int*   ei    = (const int*)d_in[1];   // [2, E]
    const int*   batch = (const int*)d_in[2];
    const float* eps0  = (const float*)d_in[3];
    const float* w1_0  = (const float*)d_in[4];
    const float* b1_0  = (const float*)d_in[5];
    const float* w2_0  = (const float*)d_in[6];
    const float* b2_0  = (const float*)d_in[7];
    const float* eps_r = (const float*)d_in[8];
    const float* w1_r  = (const float*)d_in[9];
    const float* b1_r  = (const float*)d_in[10];
    const float* w2_r  = (const float*)d_in[11];
    const float* b2_r  = (const float*)d_in[12];
    const float* w_out = (const float*)d_in[13];
    const float* b_out = (const float*)d_in[14];

    const int* src = ei;
    const int* dst = ei + EE;

    __half *xpad, *hbuf;
    uint16_t *agh;
    int *deg, *off, *cur, *edge, *part, *bsum;
    cudaGetSymbolAddress((void**)&xpad, g_xpad);
    cudaGetSymbolAddress((void**)&hbuf, g_hbuf);
    cudaGetSymbolAddress((void**)&agh,  g_aggh);
    cudaGetSymbolAddress((void**)&deg,  g_deg);
    cudaGetSymbolAddress((void**)&off,  g_off);
    cudaGetSymbolAddress((void**)&cur,  g_cur);
    cudaGetSymbolAddress((void**)&edge, g_edge);
    cudaGetSymbolAddress((void**)&part, g_part);
    cudaGetSymbolAddress((void**)&bsum, g_bsum);

    float* outp = (float*)d_out;
    const int TB = 256;
    constexpr int TPB = 2;
    const int mlp_grid = (NN + 128 * TPB - 1) / (128 * TPB);   // 391

    // ---- CSR build (one-time) + prep: 5 launches ----
    pad_init_kernel<<<(NN * 32 + TB - 1) / TB, TB>>>(x, xpad, deg);
    count_deg_kernel<<<(EE + TB - 1) / TB, TB>>>(dst, deg, outp, b_out);
    scan_block_kernel<<<98, 1024>>>(deg, part, bsum);
    scan_add_kernel<<<98, 1024>>>(part, bsum, off, cur);
    place_kernel<<<(EE + TB - 1) / TB, TB>>>(src, dst, cur, edge);

    // ---- Layer 0 (K=32) ----
    gather_kernel<32><<<(NN * 4 + 255) / 256, 256>>>(xpad, agh, off, deg, edge, eps0);
    fused_mlp_kernel<32, false, TPB><<<mlp_grid, 128>>>(agh, w1_0, b1_0, w2_0, b2_0, 30,
                                                        hbuf, nullptr, nullptr, nullptr);
    // ---- Layers 1..2 ----
    for (int i = 0; i < 2; i++) {
        gather_kernel<64><<<(NN * 8 + 255) / 256, 256>>>(hbuf, agh, off, deg, edge, eps_r + i);
        fused_mlp_kernel<64, false, TPB><<<mlp_grid, 128>>>(agh, w1_r + i * 4096, b1_r + i * 64,
                                                            w2_r + i * 4096, b2_r + i * 64, 64,
                                                            hbuf, nullptr, nullptr, nullptr);
    }
    // ---- Layer 3 (fused pool) ----
    gather_kernel<64><<<(NN * 8 + 255) / 256, 256>>>(hbuf, agh, off, deg, edge, eps_r + 2);
    fused_mlp_kernel<64, true, TPB><<<mlp_grid, 128>>>(agh, w1_r + 8192, b1_r + 128,
                                                       w2_r + 8192, b2_r + 128, 64,
                                                       nullptr, batch, w_out, outp);
}

// round 16
// speedup vs baseline: 1.0566x; 1.0063x over previous
#include <cuda_runtime.h>
#include <cuda_bf16.h>
#include <cuda_fp16.h>
#include <cstdint>
#include <cstring>

#define NN 100000
#define EE 1200000
#define GG 128

// Scratch (device globals: no allocation anywhere)
__device__ __align__(16) __half g_xpad[NN * 32];
__device__ __align__(16) __half g_hbuf[NN * 64];
__device__ __align__(16) uint16_t g_aggh[NN * 64];
__device__ int   g_deg[NN];
__device__ int   g_off[NN];
__device__ int   g_cur[NN];
__device__ int   g_edge[EE];
__device__ int   g_bsum[128];     // scan flags: total+1 per block (0 = not ready)

// ---------------------------------------------------------------------------
// Helpers
// ---------------------------------------------------------------------------
__device__ __forceinline__ uint32_t smem_u32(const void* p) {
    uint32_t a;
    asm("{ .reg .u64 t; cvta.to.shared.u64 t, %1; cvt.u32.u64 %0, t; }"
        : "=r"(a) : "l"(p));
    return a;
}

// Swizzled row base: swz(row*128 + kb) == rb(row) ^ kb  for kb < 128 (no carry)
__device__ __forceinline__ uint32_t rb(int row) {
    return (uint32_t)(row * 128) ^ (((uint32_t)row & 7u) << 4);
}

__device__ __forceinline__ void ldm_x4(uint32_t r[4], uint32_t addr) {
    asm volatile("ldmatrix.sync.aligned.m8n8.x4.shared.b16 {%0,%1,%2,%3}, [%4];"
                 : "=r"(r[0]), "=r"(r[1]), "=r"(r[2]), "=r"(r[3]) : "r"(addr));
}

__device__ __forceinline__ void mma_bf16(float c[4], const uint32_t a[4],
                                         uint32_t b0, uint32_t b1) {
    asm volatile(
        "mma.sync.aligned.m16n8k16.row.col.f32.bf16.bf16.f32 "
        "{%0,%1,%2,%3}, {%4,%5,%6,%7}, {%8,%9}, {%0,%1,%2,%3};"
        : "+f"(c[0]), "+f"(c[1]), "+f"(c[2]), "+f"(c[3])
        : "r"(a[0]), "r"(a[1]), "r"(a[2]), "r"(a[3]), "r"(b0), "r"(b1));
}

__device__ __forceinline__ void split_bf16(float v, __nv_bfloat16& h, __nv_bfloat16& l) {
    h = __float2bfloat16_rn(v);
    l = __float2bfloat16_rn(v - __bfloat162float(h));
}

// Split+pack two floats: returns hi-pair (bf16x2 bits), writes lo-pair.
__device__ __forceinline__ uint32_t packsplit(float a, float b, uint32_t& lopack) {
    __nv_bfloat16 ha, la, hb, lb;
    split_bf16(a, ha, la);
    split_bf16(b, hb, lb);
    uint16_t ua, ub, va, vb;
    memcpy(&ua, &ha, 2); memcpy(&ub, &hb, 2);
    memcpy(&va, &la, 2); memcpy(&vb, &lb, 2);
    lopack = (uint32_t)va | ((uint32_t)vb << 16);
    return (uint32_t)ua | ((uint32_t)ub << 16);
}

// Pack two floats as plain bf16x2.
__device__ __forceinline__ uint32_t packbf2(float a, float b) {
    __nv_bfloat162 p = __floats2bfloat162_rn(a, b);
    uint32_t u;
    memcpy(&u, &p, 4);
    return u;
}

// ---------------------------------------------------------------------------
// CSR build + prep
// ---------------------------------------------------------------------------
__global__ void pad_init_kernel(const float* __restrict__ x,
                                __half* __restrict__ xpad,
                                int* __restrict__ deg) {
    int i = blockIdx.x * blockDim.x + threadIdx.x;
    if (i >= NN * 32) return;
    int n = i >> 5, c = i & 31;
    xpad[i] = __float2half(c < 30 ? x[n * 30 + c] : 0.0f);
    if (c == 0) deg[n] = 0;
}

__global__ void count_deg_kernel(const int* __restrict__ dst, int* __restrict__ deg,
                                 float* __restrict__ outp,
                                 const float* __restrict__ b_out,
                                 int* __restrict__ flag) {
    int e = blockIdx.x * blockDim.x + threadIdx.x;
    if (e < EE) atomicAdd(&deg[__ldg(dst + e)], 1);
    if (blockIdx.x == 0 && threadIdx.x < GG) outp[threadIdx.x] = b_out[0];
    if (blockIdx.x == 1 && threadIdx.x < 128) flag[threadIdx.x] = 0;  // reset scan flags
}

// Single-pass scan with decoupled lookback. 98 blocks (all resident in one
// wave, so predecessor spin is deadlock-free). flag[b] = block_total + 1.
__global__ void scan_fused_kernel(const int* __restrict__ deg,
                                  int* __restrict__ off, int* __restrict__ cur,
                                  int* __restrict__ flag) {
    __shared__ int wt[32];
    __shared__ int s_prev;
    int tid = threadIdx.x;
    int lane = tid & 31, w = tid >> 5;
    int gid = blockIdx.x * 1024 + tid;
    int v = (gid < NN) ? deg[gid] : 0;

    // Inclusive scan within warp
    int x = v;
#pragma unroll
    for (int ofs = 1; ofs < 32; ofs <<= 1) {
        int t = __shfl_up_sync(0xFFFFFFFF, x, ofs);
        if (lane >= ofs) x += t;
    }
    if (lane == 31) wt[w] = x;
    __syncthreads();
    if (w == 0) {
        int y = wt[lane];
#pragma unroll
        for (int ofs = 1; ofs < 32; ofs <<= 1) {
            int t = __shfl_up_sync(0xFFFFFFFF, y, ofs);
            if (lane >= ofs) y += t;
        }
        wt[lane] = y;
    }
    __syncthreads();
    int pre = (w > 0) ? wt[w - 1] : 0;
    int incl = x + pre;
    int btotal = wt[31];

    // Publish this block's total (nonzero-encoded), then parallel lookback.
    if (tid == 0) atomicExch(&flag[blockIdx.x], btotal + 1);
    if (w == 0) {
        int p = 0;
        for (int i = lane; i < blockIdx.x; i += 32) {
            int f;
            do { f = atomicAdd(&flag[i], 0); } while (f == 0);
            p += f - 1;
        }
#pragma unroll
        for (int ofs = 16; ofs >= 1; ofs >>= 1)
            p += __shfl_xor_sync(0xFFFFFFFF, p, ofs);
        if (lane == 0) s_prev = p;
    }
    __syncthreads();

    if (gid >= NN) return;
    int o = incl - v + s_prev;
    off[gid] = o;
    cur[gid] = o;
}

__global__ void place_kernel(const int* __restrict__ src, const int* __restrict__ dst,
                             int* __restrict__ cur, int* __restrict__ edge) {
    int e = blockIdx.x * blockDim.x + threadIdx.x;
    if (e >= EE) return;
    int d = __ldg(dst + e);
    int p = atomicAdd(&cur[d], 1);
    edge[p] = __ldg(src + e);
}

// ---------------------------------------------------------------------------
// Gather (R12-proven): acc = (1+eps)*h[n] + sum h[src_e] over fp16 rows;
// K/8 lanes per node (16B each); fp32 accumulate; edge loop unrolled x4;
// output plain bf16 (A-hi only).
// ---------------------------------------------------------------------------
template <int K>
__global__ __launch_bounds__(256) void gather_kernel(
    const __half* __restrict__ hin,
    uint16_t* __restrict__ agh,
    const int* __restrict__ off, const int* __restrict__ deg,
    const int* __restrict__ edge, const float* __restrict__ eps) {
    constexpr int L = K / 8;             // lanes per node (16B each)
    const int tid = blockIdx.x * 256 + threadIdx.x;
    const int gn = tid / L;
    const int sub = tid % L;
    if (gn >= NN) return;

    float acc[8];
    const float s = 1.0f + __ldg(eps);
    {
        uint4 u = *(const uint4*)(hin + (size_t)gn * K + sub * 8);
        const __half2* hp = (const __half2*)&u;
#pragma unroll
        for (int j = 0; j < 4; j++) {
            float2 f = __half22float2(hp[j]);
            acc[j * 2 + 0] = s * f.x;
            acc[j * 2 + 1] = s * f.y;
        }
    }

    const int e0 = __ldg(off + gn);
    const int dg = __ldg(deg + gn);
    int e = 0;
    for (; e + 4 <= dg; e += 4) {
        int sn0 = __ldg(edge + e0 + e);
        int sn1 = __ldg(edge + e0 + e + 1);
        int sn2 = __ldg(edge + e0 + e + 2);
        int sn3 = __ldg(edge + e0 + e + 3);
        uint4 u0 = *(const uint4*)(hin + (size_t)sn0 * K + sub * 8);
        uint4 u1 = *(const uint4*)(hin + (size_t)sn1 * K + sub * 8);
        uint4 u2 = *(const uint4*)(hin + (size_t)sn2 * K + sub * 8);
        uint4 u3 = *(const uint4*)(hin + (size_t)sn3 * K + sub * 8);
        const __half2* p0 = (const __half2*)&u0;
        const __half2* p1 = (const __half2*)&u1;
        const __half2* p2 = (const __half2*)&u2;
        const __half2* p3 = (const __half2*)&u3;
#pragma unroll
        for (int j = 0; j < 4; j++) {
            float2 f0 = __half22float2(p0[j]);
            float2 f1 = __half22float2(p1[j]);
            float2 f2 = __half22float2(p2[j]);
            float2 f3 = __half22float2(p3[j]);
            acc[j * 2 + 0] += (f0.x + f1.x) + (f2.x + f3.x);
            acc[j * 2 + 1] += (f0.y + f1.y) + (f2.y + f3.y);
        }
    }
    for (; e < dg; e++) {
        int sn0 = __ldg(edge + e0 + e);
        uint4 ua = *(const uint4*)(hin + (size_t)sn0 * K + sub * 8);
        const __half2* pa = (const __half2*)&ua;
#pragma unroll
        for (int j = 0; j < 4; j++) {
            float2 fa = __half22float2(pa[j]);
            acc[j * 2 + 0] += fa.x;
            acc[j * 2 + 1] += fa.y;
        }
    }

    uint4 hv;
    hv.x = packbf2(acc[0], acc[1]);
    hv.y = packbf2(acc[2], acc[3]);
    hv.z = packbf2(acc[4], acc[5]);
    hv.w = packbf2(acc[6], acc[7]);
    *(uint4*)(agh + (size_t)gn * K + sub * 8) = hv;
}

// ---------------------------------------------------------------------------
// GEMM core: C[2][8][4] += A(bf16) @ (Whi + Wlo), 2-term split.
// ---------------------------------------------------------------------------
template <int KS>
__device__ __forceinline__ void do_gemm(float c[2][8][4],
                                        const uint32_t aB[2],
                                        const uint32_t bBH[4], const uint32_t bBL[4]) {
#pragma unroll
    for (int ks = 0; ks < KS; ks++) {
        const uint32_t kx = ks * 32;
        uint32_t aF[2][4];
#pragma unroll
        for (int m = 0; m < 2; m++) ldm_x4(aF[m], aB[m] ^ kx);
#pragma unroll
        for (int p = 0; p < 4; p++) {
            uint32_t bh[4], bl[4];
            ldm_x4(bh, bBH[p] ^ kx);
            ldm_x4(bl, bBL[p] ^ kx);
#pragma unroll
            for (int s = 0; s < 2; s++) {
                const int nt = 2 * p + s;
#pragma unroll
                for (int m = 0; m < 2; m++) {
                    mma_bf16(c[m][nt], aF[m], bh[s * 2], bh[s * 2 + 1]);
                    mma_bf16(c[m][nt], aF[m], bl[s * 2], bl[s * 2 + 1]);
                }
            }
        }
    }
}

// ---------------------------------------------------------------------------
// Fused GIN MLP (R12-proven): out = relu(A@W1+b1)@W2+b2. Each block stages
// W1+W2 hi/lo ONCE, then processes TPB 128-node tiles.
// ---------------------------------------------------------------------------
template <int K_IN, bool POOL, int TPB>
__global__ __launch_bounds__(128) void fused_mlp_kernel(
    const uint16_t* __restrict__ Ah,
    const float* __restrict__ W1, const float* __restrict__ b1,
    const float* __restrict__ W2, const float* __restrict__ b2, int w1Rows,
    __half* __restrict__ out,
    const int* __restrict__ batch,
    const float* __restrict__ wout, float* __restrict__ outp) {
    __shared__ __align__(128) char sA[128 * 128];      // 16KB
    __shared__ __align__(128) char sW1_hi[64 * 128];   // 8KB
    __shared__ __align__(128) char sW1_lo[64 * 128];   // 8KB
    __shared__ __align__(128) char sW2_hi[64 * 128];   // 8KB
    __shared__ __align__(128) char sW2_lo[64 * 128];   // 8KB

    const int tid  = threadIdx.x;
    const int warp = tid >> 5;
    const int lane = tid & 31;
    const int qr = lane >> 2;
    const int qc = lane & 3;
    const int g  = lane >> 3;
    const int li = lane & 7;

    const uint32_t sA_u    = smem_u32(sA);
    const uint32_t sW1hi_u = smem_u32(sW1_hi);
    const uint32_t sW1lo_u = smem_u32(sW1_lo);
    const uint32_t sW2hi_u = smem_u32(sW2_hi);
    const uint32_t sW2lo_u = smem_u32(sW2_lo);

    // ---- Stage W1 + W2 transposed (once per block) ----
    for (int i = tid; i < 64 * 32; i += 128) {
        int n = i >> 5, c2 = i & 31;
        int k0 = c2 * 2;
        uint32_t o = rb(n) ^ (uint32_t)(k0 * 2);
        float w0  = (k0     < w1Rows) ? W1[(k0    ) * 64 + n] : 0.0f;
        float w1v = (k0 + 1 < w1Rows) ? W1[(k0 + 1) * 64 + n] : 0.0f;
        uint32_t lo, hi = packsplit(w0, w1v, lo);
        *(uint32_t*)(sW1_hi + o) = hi;
        *(uint32_t*)(sW1_lo + o) = lo;
        hi = packsplit(W2[k0 * 64 + n], W2[(k0 + 1) * 64 + n], lo);
        *(uint32_t*)(sW2_hi + o) = hi;
        *(uint32_t*)(sW2_lo + o) = lo;
    }

    // ---- Precompute ldmatrix lane bases (constant across tiles) ----
    uint32_t aB[2];
#pragma unroll
    for (int m = 0; m < 2; m++) {
        int rowA = warp * 32 + m * 16 + li + (g & 1) * 8;
        uint32_t ka = (uint32_t)((g >> 1) * 16);
        aB[m] = sA_u + (rb(rowA) ^ ka);
    }
    uint32_t b1H[4], b1L[4], b2H[4], b2L[4];
#pragma unroll
    for (int p = 0; p < 4; p++) {
        int rowB = p * 16 + ((g >> 1) & 1) * 8 + li;
        uint32_t kb = (uint32_t)((g & 1) * 16);
        uint32_t r = rb(rowB) ^ kb;
        b1H[p] = sW1hi_u + r;
        b1L[p] = sW1lo_u + r;
        b2H[p] = sW2hi_u + r;
        b2L[p] = sW2lo_u + r;
    }

    constexpr int CH = K_IN / 8;  // 16B chunks of data per row

    for (int t = 0; t < TPB; t++) {
        const int base = (blockIdx.x * TPB + t) * 128;
        if (base >= NN) break;

        // Guard: previous tile's GEMM2 reads of sA must finish (also covers
        // the once-per-block W staging on the first iteration).
        __syncthreads();

        // ---- Stage A: pure 16B copies ----
        for (int idx = tid; idx < 128 * CH; idx += 128) {
            int row = idx / CH, cch = idx % CH;
            int gn = base + row;
            uint4 vh = make_uint4(0, 0, 0, 0);
            if (gn < NN) vh = *(const uint4*)(Ah + (size_t)gn * K_IN + cch * 8);
            *(uint4*)(sA + (rb(row) ^ (uint32_t)(cch * 16))) = vh;
        }
        __syncthreads();

        float c[2][8][4];
#pragma unroll
        for (int m = 0; m < 2; m++)
#pragma unroll
            for (int n = 0; n < 8; n++)
#pragma unroll
                for (int j = 0; j < 4; j++) c[m][n][j] = 0.0f;

        // ---- GEMM1 ----
        do_gemm<K_IN / 16>(c, aB, b1H, b1L);

        // ---- Epilogue 1: h = relu(C+b1) -> bf16 into sA (own-warp rows) ----
#pragma unroll
        for (int m = 0; m < 2; m++) {
            int r0 = warp * 32 + m * 16 + qr;
            uint32_t rb0 = rb(r0), rb1 = rb(r0 + 8);
#pragma unroll
            for (int nt = 0; nt < 8; nt++) {
                uint32_t cb = (uint32_t)(nt * 16 + qc * 4);
                int col = nt * 8 + qc * 2;
                float bv0 = __ldg(b1 + col), bv1 = __ldg(b1 + col + 1);
                float v0 = fmaxf(c[m][nt][0] + bv0, 0.0f);
                float v1 = fmaxf(c[m][nt][1] + bv1, 0.0f);
                float v2 = fmaxf(c[m][nt][2] + bv0, 0.0f);
                float v3 = fmaxf(c[m][nt][3] + bv1, 0.0f);
                *(uint32_t*)(sA + (rb0 ^ cb)) = packbf2(v0, v1);
                *(uint32_t*)(sA + (rb1 ^ cb)) = packbf2(v2, v3);
            }
        }
        // No barrier: GEMM2 reads only this warp's own sA rows.

#pragma unroll
        for (int m = 0; m < 2; m++)
#pragma unroll
            for (int n = 0; n < 8; n++)
#pragma unroll
                for (int j = 0; j < 4; j++) c[m][n][j] = 0.0f;

        // ---- GEMM2 ----
        do_gemm<4>(c, aB, b2H, b2L);

        // ---- Epilogue 2 ----
        if (!POOL) {
#pragma unroll
            for (int m = 0; m < 2; m++) {
                int r0 = warp * 32 + m * 16 + qr;
                int gn0 = base + r0, gn1 = gn0 + 8;
#pragma unroll
                for (int nt = 0; nt < 8; nt++) {
                    int col = nt * 8 + qc * 2;
                    float bv0 = __ldg(b2 + col), bv1 = __ldg(b2 + col + 1);
                    if (gn0 < NN)
                        *(__half2*)(out + (size_t)gn0 * 64 + col) =
                            __floats2half2_rn(c[m][nt][0] + bv0, c[m][nt][1] + bv1);
                    if (gn1 < NN)
                        *(__half2*)(out + (size_t)gn1 * 64 + col) =
                            __floats2half2_rn(c[m][nt][2] + bv0, c[m][nt][3] + bv1);
                }
            }
        } else {
#pragma unroll
            for (int m = 0; m < 2; m++) {
                int r0 = warp * 32 + m * 16 + qr;
                int gn0 = base + r0, gn1 = gn0 + 8;
                float s0 = 0.0f, s1 = 0.0f;
#pragma unroll
                for (int nt = 0; nt < 8; nt++) {
                    int col = nt * 8 + qc * 2;
                    float bv0 = __ldg(b2 + col), bv1 = __ldg(b2 + col + 1);
                    float w0 = __ldg(wout + col), w1 = __ldg(wout + col + 1);
                    s0 += (c[m][nt][0] + bv0) * w0 + (c[m][nt][1] + bv1) * w1;
                    s1 += (c[m][nt][2] + bv0) * w0 + (c[m][nt][3] + bv1) * w1;
                }
                s0 += __shfl_xor_sync(0xFFFFFFFF, s0, 1);
                s0 += __shfl_xor_sync(0xFFFFFFFF, s0, 2);
                s1 += __shfl_xor_sync(0xFFFFFFFF, s1, 1);
                s1 += __shfl_xor_sync(0xFFFFFFFF, s1, 2);
                if (qc == 0) {
                    if (gn0 < NN) atomicAdd(&outp[__ldg(batch + gn0)], s0);
                    if (gn1 < NN) atomicAdd(&outp[__ldg(batch + gn1)], s1);
                }
            }
        }
    }
}

// ---------------------------------------------------------------------------
extern "C" void kernel_launch(void* const* d_in, const int* in_sizes, int n_in,
                              void* d_out, int out_size) {
    const float* x     = (const float*)d_in[0];
    const int*   ei    = (const int*)d_in[1];   // [2, E]
    const int*   batch = (const int*)d_in[2];
    const float* eps0  = (const float*)d_in[3];
    const float* w1_0  = (const float*)d_in[4];
    const float* b1_0  = (const float*)d_in[5];
    const float* w2_0  = (const float*)d_in[6];
    const float* b2_0  = (const float*)d_in[7];
    const float* eps_r = (const float*)d_in[8];
    const float* w1_r  = (const float*)d_in[9];
    const float* b1_r  = (const float*)d_in[10];
    const float* w2_r  = (const float*)d_in[11];
    const float* b2_r  = (const float*)d_in[12];
    const float* w_out = (const float*)d_in[13];
    const float* b_out = (const float*)d_in[14];

    const int* src = ei;
    const int* dst = ei + EE;

    __half *xpad, *hbuf;
    uint16_t *agh;
    int *deg, *off, *cur, *edge, *bsum;
    cudaGetSymbolAddress((void**)&xpad, g_xpad);
    cudaGetSymbolAddress((void**)&hbuf, g_hbuf);
    cudaGetSymbolAddress((void**)&agh,  g_aggh);
    cudaGetSymbolAddress((void**)&deg,  g_deg);
    cudaGetSymbolAddress((void**)&off,  g_off);
    cudaGetSymbolAddress((void**)&cur,  g_cur);
    cudaGetSymbolAddress((void**)&edge, g_edge);
    cudaGetSymbolAddress((void**)&bsum, g_bsum);

    float* outp = (float*)d_out;
    const int TB = 256;
    constexpr int TPB = 2;
    const int mlp_grid = (NN + 128 * TPB - 1) / (128 * TPB);   // 391

    // ---- CSR build (one-time) + prep: 4 launches ----
    pad_init_kernel<<<(NN * 32 + TB - 1) / TB, TB>>>(x, xpad, deg);
    count_deg_kernel<<<(EE + TB - 1) / TB, TB>>>(dst, deg, outp, b_out, bsum);
    scan_fused_kernel<<<98, 1024>>>(deg, off, cur, bsum);
    place_kernel<<<(EE + TB - 1) / TB, TB>>>(src, dst, cur, edge);

    // ---- Layer 0 (K=32) ----
    gather_kernel<32><<<(NN * 4 + 255) / 256, 256>>>(xpad, agh, off, deg, edge, eps0);
    fused_mlp_kernel<32, false, TPB><<<mlp_grid, 128>>>(agh, w1_0, b1_0, w2_0, b2_0, 30,
                                                        hbuf, nullptr, nullptr, nullptr);
    // ---- Layers 1..2 ----
    for (int i = 0; i < 2; i++) {
        gather_kernel<64><<<(NN * 8 + 255) / 256, 256>>>(hbuf, agh, off, deg, edge, eps_r + i);
        fused_mlp_kernel<64, false, TPB><<<mlp_grid, 128>>>(agh, w1_r + i * 4096, b1_r + i * 64,
                                                            w2_r + i * 4096, b2_r + i * 64, 64,
                                                            hbuf, nullptr, nullptr, nullptr);
    }
    // ---- Layer 3 (fused pool) ----
    gather_kernel<64><<<(NN * 8 + 255) / 256, 256>>>(hbuf, agh, off, deg, edge, eps_r + 2);
    fused_mlp_kernel<64, true, TPB><<<mlp_grid, 128>>>(agh, w1_r + 8192, b1_r + 128,
                                                       w2_r + 8192, b2_r + 128, 64,
                                                       nullptr, batch, w_out, outp);
}